// round 1
// baseline (speedup 1.0000x reference)
#include <cuda_runtime.h>
#include <cuda_bf16.h>
#include <math.h>

// ---------------------------------------------------------------------------
// MPNN on GB300. Strategy:
//  - Build CSR-by-destination each call (deg atomics -> single-block scan -> fill).
//  - Gathers are pull-style: one warp per destination node, 2 feats/lane (float2).
//  - GEMMs: block = 256 thr = 64 nodes x 64 cols; W in smem, input tile in smem
//    (pitch-padded), each thread = 1 node x 16 cols, 16 fp32 accumulators.
//  - Readout: pooled part collapses to one scalar per graph.
// ---------------------------------------------------------------------------

#define MAXN 65536
#define MAXE 1048576
#define MAXG 512
#define FD   64

__device__ int   g_deg[MAXN];
__device__ int   g_rowptr[MAXN];
__device__ int   g_wptr[MAXN];
__device__ int   g_srcidx[MAXE];
__device__ float g_dinv[MAXN];
__device__ int   g_degmax;

__device__ float g_h[MAXN * FD];
__device__ float g_nagg[MAXN * FD];
__device__ float g_msg[MAXN * FD];
__device__ float g_eemb[MAXN * FD];
__device__ float g_curA[MAXN * FD];
__device__ float g_curB[MAXN * FD];

__device__ float g_means[MAXG * FD];
__device__ float g_cnt[MAXG];
__device__ float g_gconst[MAXG];

// ---------------------------------------------------------------------------
__global__ void k_zero(int n) {
    int i = blockIdx.x * blockDim.x + threadIdx.x;
    int stride = gridDim.x * blockDim.x;
    for (int t = i; t < n; t += stride) g_deg[t] = 0;
    for (int t = i; t < MAXG * FD; t += stride) g_means[t] = 0.f;
    for (int t = i; t < MAXG; t += stride) g_cnt[t] = 0.f;
    if (i == 0) g_degmax = 0;
}

__global__ void k_deg(const int* __restrict__ col, int E) {
    int i = blockIdx.x * blockDim.x + threadIdx.x;
    if (i < E) atomicAdd(&g_deg[col[i]], 1);
}

// single-block exclusive scan over deg -> rowptr/wptr, plus dinv and degmax
__global__ void k_scan(int n) {
    __shared__ int sums[1024];
    __shared__ int smax[1024];
    int t = threadIdx.x;
    int chunk = (n + 1023) >> 10;
    int s = t * chunk;
    int e = min(s + chunk, n);
    int loc = 0, mx = 0;
    for (int i = s; i < e; i++) { int d = g_deg[i]; loc += d; mx = max(mx, d); }
    sums[t] = loc;
    smax[t] = mx;
    __syncthreads();
    // Hillis-Steele inclusive scan
    for (int off = 1; off < 1024; off <<= 1) {
        int v = (t >= off) ? sums[t - off] : 0;
        __syncthreads();
        sums[t] += v;
        __syncthreads();
    }
    int run = (t == 0) ? 0 : sums[t - 1];
    for (int i = s; i < e; i++) {
        int d = g_deg[i];
        g_rowptr[i] = run;
        g_wptr[i]   = run;
        g_dinv[i]   = (d > 0) ? (1.0f / (float)d) : 0.0f;
        run += d;
    }
    for (int off = 512; off > 0; off >>= 1) {
        if (t < off) smax[t] = max(smax[t], smax[t + off]);
        __syncthreads();
    }
    if (t == 0) g_degmax = max(smax[0], 1);
}

__global__ void k_fill(const int* __restrict__ row, const int* __restrict__ col, int E) {
    int i = blockIdx.x * blockDim.x + threadIdx.x;
    if (i < E) {
        int p = atomicAdd(&g_wptr[col[i]], 1);
        g_srcidx[p] = row[i];
    }
}

// cur = relu(x @ W_init) ; h = relu(x @ W_e1) padded with 0 in col 63
__global__ void k_init(const float* __restrict__ x, const float* __restrict__ Wi,
                       const float* __restrict__ We1, int n, int nobs) {
    int t = blockIdx.x * blockDim.x + threadIdx.x;
    if (t >= n * 64) return;
    int node = t >> 6, c = t & 63;
    const float* xr = x + node * nobs;
    float s1 = 0.f, s2 = 0.f;
    for (int j = 0; j < nobs; j++) {
        float xv = __ldg(&xr[j]);
        s1 += xv * __ldg(&Wi[j * 64 + c]);
        if (c < 63) s2 += xv * __ldg(&We1[j * 63 + c]);
    }
    g_curA[t] = fmaxf(s1, 0.f);
    g_h[t]    = (c < 63) ? fmaxf(s2, 0.f) : 0.f;
}

// pull-gather: out[v] = dinv[v] * sum_{u in N(v)} feat[u]; optionally col63 = deg/degmax
__global__ void k_gather(const float* __restrict__ feat, float* __restrict__ out,
                         int n, int degcol) {
    int w = (blockIdx.x * blockDim.x + threadIdx.x) >> 5;
    int lane = threadIdx.x & 31;
    if (w >= n) return;
    int start = g_rowptr[w];
    int d = g_deg[w];
    const float2* f2 = (const float2*)feat;
    float ax = 0.f, ay = 0.f;
    int i = 0;
    for (; i + 4 <= d; i += 4) {
        int s0 = g_srcidx[start + i];
        int s1 = g_srcidx[start + i + 1];
        int s2 = g_srcidx[start + i + 2];
        int s3 = g_srcidx[start + i + 3];
        float2 v0 = f2[s0 * 32 + lane];
        float2 v1 = f2[s1 * 32 + lane];
        float2 v2 = f2[s2 * 32 + lane];
        float2 v3 = f2[s3 * 32 + lane];
        ax += v0.x + v1.x + v2.x + v3.x;
        ay += v0.y + v1.y + v2.y + v3.y;
    }
    for (; i < d; i++) {
        int s = g_srcidx[start + i];
        float2 v = f2[s * 32 + lane];
        ax += v.x; ay += v.y;
    }
    float sc = g_dinv[w];
    ax *= sc; ay *= sc;
    if (degcol && lane == 31) ay = (float)d / (float)g_degmax;
    ((float2*)out)[w * 32 + lane] = make_float2(ax, ay);
}

// C[n,64] = relu( concat(A[n,64], B[n,64]) @ W[K,64] ), K in {64,128}
template <int K>
__global__ __launch_bounds__(256) void k_gemm(const float* __restrict__ A,
                                              const float* __restrict__ B,
                                              const float* __restrict__ W,
                                              float* __restrict__ C, int n) {
    extern __shared__ float sm[];
    const int PITCH = K + 4;
    float* Ws  = sm;            // K*64
    float* ins = sm + K * 64;   // 64*PITCH
    int tid = threadIdx.x;
    int node0 = blockIdx.x * 64;

    for (int idx = tid; idx < K * 16; idx += 256)
        ((float4*)Ws)[idx] = __ldg((const float4*)W + idx);

    for (int idx = tid; idx < 1024; idx += 256) {
        int r = idx >> 4, c4 = (idx & 15) << 2;
        float4 v = (node0 + r < n) ? *(const float4*)&A[(size_t)(node0 + r) * 64 + c4]
                                   : make_float4(0.f, 0.f, 0.f, 0.f);
        int o = r * PITCH + c4;
        ins[o] = v.x; ins[o + 1] = v.y; ins[o + 2] = v.z; ins[o + 3] = v.w;
    }
    if (K == 128) {
        for (int idx = tid; idx < 1024; idx += 256) {
            int r = idx >> 4, c4 = (idx & 15) << 2;
            float4 v = (node0 + r < n) ? *(const float4*)&B[(size_t)(node0 + r) * 64 + c4]
                                       : make_float4(0.f, 0.f, 0.f, 0.f);
            int o = r * PITCH + 64 + c4;
            ins[o] = v.x; ins[o + 1] = v.y; ins[o + 2] = v.z; ins[o + 3] = v.w;
        }
    }
    __syncthreads();

    int r  = tid >> 2;
    int c0 = (tid & 3) * 16;
    float acc[16];
#pragma unroll
    for (int j = 0; j < 16; j++) acc[j] = 0.f;
    const float* insr = &ins[r * PITCH];

#pragma unroll 4
    for (int k = 0; k < K; k += 4) {
        float4 a = *(const float4*)&insr[k];
#pragma unroll
        for (int kk = 0; kk < 4; kk++) {
            float av = (kk == 0) ? a.x : (kk == 1) ? a.y : (kk == 2) ? a.z : a.w;
            const float* wr = &Ws[(k + kk) * 64 + c0];
            float4 w0 = *(const float4*)&wr[0];
            float4 w1 = *(const float4*)&wr[4];
            float4 w2 = *(const float4*)&wr[8];
            float4 w3 = *(const float4*)&wr[12];
            acc[0]  += av * w0.x; acc[1]  += av * w0.y; acc[2]  += av * w0.z; acc[3]  += av * w0.w;
            acc[4]  += av * w1.x; acc[5]  += av * w1.y; acc[6]  += av * w1.z; acc[7]  += av * w1.w;
            acc[8]  += av * w2.x; acc[9]  += av * w2.y; acc[10] += av * w2.z; acc[11] += av * w2.w;
            acc[12] += av * w3.x; acc[13] += av * w3.y; acc[14] += av * w3.z; acc[15] += av * w3.w;
        }
    }

    if (node0 + r < n) {
        float* Cr = &C[(size_t)(node0 + r) * 64 + c0];
#pragma unroll
        for (int q = 0; q < 4; q++) {
            float4 o;
            o.x = fmaxf(acc[q * 4 + 0], 0.f);
            o.y = fmaxf(acc[q * 4 + 1], 0.f);
            o.z = fmaxf(acc[q * 4 + 2], 0.f);
            o.w = fmaxf(acc[q * 4 + 3], 0.f);
            *(float4*)&Cr[q * 4] = o;
        }
    }
}

// per-graph feature sums + counts (local run-length accumulation, then atomic)
__global__ void k_means(const float* __restrict__ cur, const int* __restrict__ batch, int n) {
    const int RPT = 16;
    int t = blockIdx.x * blockDim.x + threadIdx.x;
    int c  = t & 63;
    int rg = t >> 6;
    int n0 = rg * RPT;
    if (n0 >= n) return;
    int curb = __ldg(&batch[n0]);
    float acc = 0.f;
    float cnt = 0.f;
    for (int i = 0; i < RPT && n0 + i < n; i++) {
        int b = __ldg(&batch[n0 + i]);
        if (b != curb) {
            atomicAdd(&g_means[curb * 64 + c], acc);
            if (c == 0) atomicAdd(&g_cnt[curb], cnt);
            acc = 0.f; cnt = 0.f; curb = b;
        }
        acc += cur[(size_t)(n0 + i) * 64 + c];
        cnt += 1.f;
    }
    atomicAdd(&g_means[curb * 64 + c], acc);
    if (c == 0) atomicAdd(&g_cnt[curb], cnt);
}

// gconst[g] = relu(mean_g @ W_pool) . W_read[:64] + b_read
__global__ void k_gconst(const float* __restrict__ Wp, const float* __restrict__ Wr,
                         const float* __restrict__ br) {
    int g = blockIdx.x;
    int t = threadIdx.x;  // 64 threads
    __shared__ float m[64];
    __shared__ float red[64];
    float cnt = g_cnt[g];
    if (cnt <= 0.f) { if (t == 0) g_gconst[g] = 0.f; return; }
    m[t] = g_means[g * 64 + t] / cnt;
    __syncthreads();
    float p = 0.f;
#pragma unroll 8
    for (int k = 0; k < 64; k++) p += m[k] * __ldg(&Wp[k * 64 + t]);
    red[t] = fmaxf(p, 0.f) * __ldg(&Wr[t]);
    __syncthreads();
    if (t < 32) {
        float s = red[t] + red[t + 32];
#pragma unroll
        for (int off = 16; off > 0; off >>= 1) s += __shfl_down_sync(0xffffffffu, s, off);
        if (t == 0) g_gconst[g] = s + __ldg(&br[0]);
    }
}

// out[n] = gconst[batch[n]] + relu(cur[n]) . W_read[64:]
__global__ void k_out(const float* __restrict__ cur, const int* __restrict__ batch,
                      const float* __restrict__ Wr, float* __restrict__ out, int n) {
    int w = (blockIdx.x * blockDim.x + threadIdx.x) >> 5;
    int lane = threadIdx.x & 31;
    if (w >= n) return;
    float f1 = cur[(size_t)w * 64 + lane];
    float f2 = cur[(size_t)w * 64 + 32 + lane];
    float s = fmaxf(f1, 0.f) * __ldg(&Wr[64 + lane]) + fmaxf(f2, 0.f) * __ldg(&Wr[96 + lane]);
#pragma unroll
    for (int off = 16; off > 0; off >>= 1) s += __shfl_down_sync(0xffffffffu, s, off);
    if (lane == 0) out[w] = s + g_gconst[__ldg(&batch[w])];
}

// ---------------------------------------------------------------------------
extern "C" void kernel_launch(void* const* d_in, const int* in_sizes, int n_in,
                              void* d_out, int out_size) {
    const float* x    = (const float*)d_in[0];
    const float* Wi   = (const float*)d_in[1];
    const float* We1  = (const float*)d_in[2];
    const float* We2  = (const float*)d_in[3];
    const float* Wmsg = (const float*)d_in[4];
    const float* Wupd = (const float*)d_in[5];
    const float* Wp   = (const float*)d_in[6];
    const float* Wr   = (const float*)d_in[7];
    const float* br   = (const float*)d_in[8];
    const int*   eidx = (const int*)d_in[9];
    const int*   batch= (const int*)d_in[10];

    int n    = in_sizes[10];
    int E    = in_sizes[9] / 2;
    int nobs = in_sizes[0] / n;
    int L    = in_sizes[4] / (128 * 64);
    const int* row = eidx;
    const int* col = eidx + E;
    float* out = (float*)d_out;

    float *curA, *curB, *hbuf, *nagg, *msg, *eemb;
    cudaGetSymbolAddress((void**)&curA, g_curA);
    cudaGetSymbolAddress((void**)&curB, g_curB);
    cudaGetSymbolAddress((void**)&hbuf, g_h);
    cudaGetSymbolAddress((void**)&nagg, g_nagg);
    cudaGetSymbolAddress((void**)&msg,  g_msg);
    cudaGetSymbolAddress((void**)&eemb, g_eemb);

    const int SMEM128 = (128 * 64 + 64 * (128 + 4)) * 4;  // 66560
    const int SMEM64  = (64 * 64 + 64 * (64 + 4)) * 4;    // 33792
    cudaFuncSetAttribute(k_gemm<128>, cudaFuncAttributeMaxDynamicSharedMemorySize, SMEM128);

    int gE = (E + 255) / 256;
    int gNF = (n * 64 + 255) / 256;
    int gW = (n * 32 + 255) / 256;           // warp-per-node kernels
    int gG = (n + 63) / 64;                  // gemm blocks
    int gM = ((((n + 15) / 16) * 64) + 255) / 256;

    k_zero<<<256, 256>>>(n);
    k_deg<<<gE, 256>>>(col, E);
    k_scan<<<1, 1024>>>(n);
    k_fill<<<gE, 256>>>(row, col, E);
    k_init<<<gNF, 256>>>(x, Wi, We1, n, nobs);

    // edge embedding
    k_gather<<<gW, 256>>>(hbuf, nagg, n, 1);
    k_gemm<64><<<gG, 256, SMEM64>>>(nagg, nullptr, We2, eemb, n);

    float* cin = curA;
    float* cout = curB;
    for (int l = 0; l < L; l++) {
        k_gather<<<gW, 256>>>(cin, nagg, n, 0);
        k_gemm<128><<<gG, 256, SMEM128>>>(nagg, eemb, Wmsg + (size_t)l * 8192, msg, n);
        k_gemm<128><<<gG, 256, SMEM128>>>(cin, msg, Wupd + (size_t)l * 8192, cout, n);
        float* tmp = cin; cin = cout; cout = tmp;
    }

    k_means<<<gM, 256>>>(cin, batch, n);
    k_gconst<<<MAXG, 64>>>(Wp, Wr, br);
    k_out<<<gW, 256>>>(cin, batch, Wr, out, n);
}

// round 2
// speedup vs baseline: 1.4997x; 1.4997x over previous
#include <cuda_runtime.h>
#include <cuda_bf16.h>
#include <math.h>

// ---------------------------------------------------------------------------
// MPNN on GB300.
//  - CSR-by-destination rebuilt each call (deg atomics -> 1-block scan -> fill).
//  - Gathers: half-warp per destination node, float4 per lane (256B/edge LDG.128).
//  - GEMMs: 256 thr = 64 nodes x 64 cols; fma.rn.f32x2 packed math (2x fp32),
//    conflict-free column-group mapping (q*4 + g*16), pitch-padded input tile.
//  - Readout pooled branch collapses to one scalar per graph.
// ---------------------------------------------------------------------------

#define MAXN 65536
#define MAXE 1048576
#define MAXG 512
#define FD   64

__device__ int   g_deg[MAXN];
__device__ int   g_rowptr[MAXN];
__device__ int   g_wptr[MAXN];
__device__ int   g_srcidx[MAXE];
__device__ float g_dinv[MAXN];
__device__ int   g_degmax;

__device__ float g_h[MAXN * FD];
__device__ float g_nagg[MAXN * FD];
__device__ float g_msg[MAXN * FD];
__device__ float g_eemb[MAXN * FD];
__device__ float g_curA[MAXN * FD];
__device__ float g_curB[MAXN * FD];

__device__ float g_means[MAXG * FD];
__device__ float g_cnt[MAXG];
__device__ float g_gconst[MAXG];

// ---------------------------------------------------------------------------
__global__ void k_zero(int n) {
    int i = blockIdx.x * blockDim.x + threadIdx.x;
    int stride = gridDim.x * blockDim.x;
    for (int t = i; t < n; t += stride) g_deg[t] = 0;
    for (int t = i; t < MAXG * FD; t += stride) g_means[t] = 0.f;
    for (int t = i; t < MAXG; t += stride) g_cnt[t] = 0.f;
    if (i == 0) g_degmax = 0;
}

__global__ void k_deg(const int* __restrict__ col, int E) {
    int i = blockIdx.x * blockDim.x + threadIdx.x;
    if (i < E) atomicAdd(&g_deg[col[i]], 1);
}

// single-block exclusive scan over deg -> rowptr/wptr, plus dinv and degmax
__global__ void k_scan(int n) {
    __shared__ int sums[1024];
    __shared__ int smax[1024];
    int t = threadIdx.x;
    int chunk = (n + 1023) >> 10;
    int s = t * chunk;
    int e = min(s + chunk, n);
    int loc = 0, mx = 0;
    for (int i = s; i < e; i++) { int d = g_deg[i]; loc += d; mx = max(mx, d); }
    sums[t] = loc;
    smax[t] = mx;
    __syncthreads();
    for (int off = 1; off < 1024; off <<= 1) {
        int v = (t >= off) ? sums[t - off] : 0;
        __syncthreads();
        sums[t] += v;
        __syncthreads();
    }
    int run = (t == 0) ? 0 : sums[t - 1];
    for (int i = s; i < e; i++) {
        int d = g_deg[i];
        g_rowptr[i] = run;
        g_wptr[i]   = run;
        g_dinv[i]   = (d > 0) ? (1.0f / (float)d) : 0.0f;
        run += d;
    }
    for (int off = 512; off > 0; off >>= 1) {
        if (t < off) smax[t] = max(smax[t], smax[t + off]);
        __syncthreads();
    }
    if (t == 0) g_degmax = max(smax[0], 1);
}

__global__ void k_fill(const int* __restrict__ row, const int* __restrict__ col, int E) {
    int i = blockIdx.x * blockDim.x + threadIdx.x;
    if (i < E) {
        int p = atomicAdd(&g_wptr[col[i]], 1);
        g_srcidx[p] = row[i];
    }
}

// cur = relu(x @ W_init) ; h = relu(x @ W_e1) padded with 0 in col 63
__global__ void k_init(const float* __restrict__ x, const float* __restrict__ Wi,
                       const float* __restrict__ We1, int n, int nobs) {
    int t = blockIdx.x * blockDim.x + threadIdx.x;
    if (t >= n * 64) return;
    int node = t >> 6, c = t & 63;
    const float* xr = x + node * nobs;
    float s1 = 0.f, s2 = 0.f;
    for (int j = 0; j < nobs; j++) {
        float xv = __ldg(&xr[j]);
        s1 += xv * __ldg(&Wi[j * 64 + c]);
        if (c < 63) s2 += xv * __ldg(&We1[j * 63 + c]);
    }
    g_curA[t] = fmaxf(s1, 0.f);
    g_h[t]    = (c < 63) ? fmaxf(s2, 0.f) : 0.f;
}

// pull-gather: half-warp per destination node, float4 per lane (16 lanes x 16B)
__global__ void k_gather(const float* __restrict__ feat, float* __restrict__ out,
                         int n, int degcol) {
    int hw = (blockIdx.x * blockDim.x + threadIdx.x) >> 4;
    int lane = threadIdx.x & 15;
    if (hw >= n) return;
    int start = g_rowptr[hw];
    int d = g_deg[hw];
    const float4* f4 = (const float4*)feat;
    float ax = 0.f, ay = 0.f, az = 0.f, aw = 0.f;
    int i = 0;
    for (; i + 4 <= d; i += 4) {
        int s0 = __ldg(&g_srcidx[start + i]);
        int s1 = __ldg(&g_srcidx[start + i + 1]);
        int s2 = __ldg(&g_srcidx[start + i + 2]);
        int s3 = __ldg(&g_srcidx[start + i + 3]);
        float4 v0 = __ldg(&f4[s0 * 16 + lane]);
        float4 v1 = __ldg(&f4[s1 * 16 + lane]);
        float4 v2 = __ldg(&f4[s2 * 16 + lane]);
        float4 v3 = __ldg(&f4[s3 * 16 + lane]);
        float bx = (v0.x + v1.x) + (v2.x + v3.x);
        float by = (v0.y + v1.y) + (v2.y + v3.y);
        float bz = (v0.z + v1.z) + (v2.z + v3.z);
        float bw = (v0.w + v1.w) + (v2.w + v3.w);
        ax += bx; ay += by; az += bz; aw += bw;
    }
    for (; i < d; i++) {
        int s = __ldg(&g_srcidx[start + i]);
        float4 v = __ldg(&f4[s * 16 + lane]);
        ax += v.x; ay += v.y; az += v.z; aw += v.w;
    }
    float sc = g_dinv[hw];
    ax *= sc; ay *= sc; az *= sc; aw *= sc;
    if (degcol && lane == 15) aw = (float)d / (float)g_degmax;
    ((float4*)out)[hw * 16 + lane] = make_float4(ax, ay, az, aw);
}

// C[n,64] = relu( concat(A[n,64], B[n,64]) @ W[K,64] ), K in {64,128}
// thread (r = tid>>2, q = tid&3) computes row r, cols {g*16 + q*4 + 0..3}, g=0..3
// packed fma.rn.f32x2: 8 FFMA2 per k-step per thread.
template <int K>
__global__ __launch_bounds__(256) void k_gemm(const float* __restrict__ A,
                                              const float* __restrict__ B,
                                              const float* __restrict__ W,
                                              float* __restrict__ C, int n) {
    extern __shared__ float sm[];
    const int PITCH = K + 4;
    float* Ws  = sm;            // K*64
    float* ins = sm + K * 64;   // 64*PITCH
    int tid = threadIdx.x;
    int node0 = blockIdx.x * 64;

    for (int idx = tid; idx < K * 16; idx += 256)
        ((float4*)Ws)[idx] = __ldg((const float4*)W + idx);

    for (int idx = tid; idx < 1024; idx += 256) {
        int r = idx >> 4, c4 = (idx & 15) << 2;
        float4 v = (node0 + r < n) ? *(const float4*)&A[(size_t)(node0 + r) * 64 + c4]
                                   : make_float4(0.f, 0.f, 0.f, 0.f);
        *(float4*)&ins[r * PITCH + c4] = v;
    }
    if (K == 128) {
        for (int idx = tid; idx < 1024; idx += 256) {
            int r = idx >> 4, c4 = (idx & 15) << 2;
            float4 v = (node0 + r < n) ? *(const float4*)&B[(size_t)(node0 + r) * 64 + c4]
                                       : make_float4(0.f, 0.f, 0.f, 0.f);
            *(float4*)&ins[r * PITCH + 64 + c4] = v;
        }
    }
    __syncthreads();

    int r = tid >> 2;
    int q = tid & 3;
    unsigned long long acc[8];
#pragma unroll
    for (int j = 0; j < 8; j++) acc[j] = 0ull;  // (0.f, 0.f)
    const float* insr = &ins[r * PITCH];

#pragma unroll 2
    for (int k = 0; k < K; k += 4) {
        float4 a = *(const float4*)&insr[k];
#pragma unroll
        for (int kk = 0; kk < 4; kk++) {
            float av = (kk == 0) ? a.x : (kk == 1) ? a.y : (kk == 2) ? a.z : a.w;
            unsigned long long av2;
            asm("mov.b64 %0, {%1, %1};" : "=l"(av2) : "f"(av));
            const float* wrow = &Ws[(k + kk) * 64 + q * 4];
#pragma unroll
            for (int g = 0; g < 4; g++) {
                ulonglong2 w = *(const ulonglong2*)&wrow[g * 16];
                asm("fma.rn.f32x2 %0, %1, %2, %0;" : "+l"(acc[g * 2])     : "l"(av2), "l"(w.x));
                asm("fma.rn.f32x2 %0, %1, %2, %0;" : "+l"(acc[g * 2 + 1]) : "l"(av2), "l"(w.y));
            }
        }
    }

    if (node0 + r < n) {
        float* Cr = &C[(size_t)(node0 + r) * 64 + q * 4];
#pragma unroll
        for (int g = 0; g < 4; g++) {
            float lo0, hi0, lo1, hi1;
            asm("mov.b64 {%0, %1}, %2;" : "=f"(lo0), "=f"(hi0) : "l"(acc[g * 2]));
            asm("mov.b64 {%0, %1}, %2;" : "=f"(lo1), "=f"(hi1) : "l"(acc[g * 2 + 1]));
            float4 o;
            o.x = fmaxf(lo0, 0.f);
            o.y = fmaxf(hi0, 0.f);
            o.z = fmaxf(lo1, 0.f);
            o.w = fmaxf(hi1, 0.f);
            *(float4*)&Cr[g * 16] = o;
        }
    }
}

// per-graph feature sums + counts (local run-length accumulation, then atomic)
__global__ void k_means(const float* __restrict__ cur, const int* __restrict__ batch, int n) {
    const int RPT = 16;
    int t = blockIdx.x * blockDim.x + threadIdx.x;
    int c  = t & 63;
    int rg = t >> 6;
    int n0 = rg * RPT;
    if (n0 >= n) return;
    int curb = __ldg(&batch[n0]);
    float acc = 0.f;
    float cnt = 0.f;
    for (int i = 0; i < RPT && n0 + i < n; i++) {
        int b = __ldg(&batch[n0 + i]);
        if (b != curb) {
            atomicAdd(&g_means[curb * 64 + c], acc);
            if (c == 0) atomicAdd(&g_cnt[curb], cnt);
            acc = 0.f; cnt = 0.f; curb = b;
        }
        acc += cur[(size_t)(n0 + i) * 64 + c];
        cnt += 1.f;
    }
    atomicAdd(&g_means[curb * 64 + c], acc);
    if (c == 0) atomicAdd(&g_cnt[curb], cnt);
}

// gconst[g] = relu(mean_g @ W_pool) . W_read[:64] + b_read
__global__ void k_gconst(const float* __restrict__ Wp, const float* __restrict__ Wr,
                         const float* __restrict__ br) {
    int g = blockIdx.x;
    int t = threadIdx.x;  // 64 threads
    __shared__ float m[64];
    __shared__ float red[64];
    float cnt = g_cnt[g];
    if (cnt <= 0.f) { if (t == 0) g_gconst[g] = 0.f; return; }
    m[t] = g_means[g * 64 + t] / cnt;
    __syncthreads();
    float p = 0.f;
#pragma unroll 8
    for (int k = 0; k < 64; k++) p += m[k] * __ldg(&Wp[k * 64 + t]);
    red[t] = fmaxf(p, 0.f) * __ldg(&Wr[t]);
    __syncthreads();
    if (t < 32) {
        float s = red[t] + red[t + 32];
#pragma unroll
        for (int off = 16; off > 0; off >>= 1) s += __shfl_down_sync(0xffffffffu, s, off);
        if (t == 0) g_gconst[g] = s + __ldg(&br[0]);
    }
}

// out[n] = gconst[batch[n]] + relu(cur[n]) . W_read[64:]
__global__ void k_out(const float* __restrict__ cur, const int* __restrict__ batch,
                      const float* __restrict__ Wr, float* __restrict__ out, int n) {
    int w = (blockIdx.x * blockDim.x + threadIdx.x) >> 5;
    int lane = threadIdx.x & 31;
    if (w >= n) return;
    float f1 = cur[(size_t)w * 64 + lane];
    float f2 = cur[(size_t)w * 64 + 32 + lane];
    float s = fmaxf(f1, 0.f) * __ldg(&Wr[64 + lane]) + fmaxf(f2, 0.f) * __ldg(&Wr[96 + lane]);
#pragma unroll
    for (int off = 16; off > 0; off >>= 1) s += __shfl_down_sync(0xffffffffu, s, off);
    if (lane == 0) out[w] = s + g_gconst[__ldg(&batch[w])];
}

// ---------------------------------------------------------------------------
extern "C" void kernel_launch(void* const* d_in, const int* in_sizes, int n_in,
                              void* d_out, int out_size) {
    const float* x    = (const float*)d_in[0];
    const float* Wi   = (const float*)d_in[1];
    const float* We1  = (const float*)d_in[2];
    const float* We2  = (const float*)d_in[3];
    const float* Wmsg = (const float*)d_in[4];
    const float* Wupd = (const float*)d_in[5];
    const float* Wp   = (const float*)d_in[6];
    const float* Wr   = (const float*)d_in[7];
    const float* br   = (const float*)d_in[8];
    const int*   eidx = (const int*)d_in[9];
    const int*   batch= (const int*)d_in[10];

    int n    = in_sizes[10];
    int E    = in_sizes[9] / 2;
    int nobs = in_sizes[0] / n;
    int L    = in_sizes[4] / (128 * 64);
    const int* row = eidx;
    const int* col = eidx + E;
    float* out = (float*)d_out;

    float *curA, *curB, *hbuf, *nagg, *msg, *eemb;
    cudaGetSymbolAddress((void**)&curA, g_curA);
    cudaGetSymbolAddress((void**)&curB, g_curB);
    cudaGetSymbolAddress((void**)&hbuf, g_h);
    cudaGetSymbolAddress((void**)&nagg, g_nagg);
    cudaGetSymbolAddress((void**)&msg,  g_msg);
    cudaGetSymbolAddress((void**)&eemb, g_eemb);

    const int SMEM128 = (128 * 64 + 64 * (128 + 4)) * 4;  // 66560
    const int SMEM64  = (64 * 64 + 64 * (64 + 4)) * 4;    // 33792
    cudaFuncSetAttribute(k_gemm<128>, cudaFuncAttributeMaxDynamicSharedMemorySize, SMEM128);

    int gE  = (E + 255) / 256;
    int gNF = (n * 64 + 255) / 256;
    int gHW = (n * 16 + 255) / 256;          // half-warp-per-node gather
    int gW  = (n * 32 + 255) / 256;          // warp-per-node (k_out)
    int gG  = (n + 63) / 64;                 // gemm blocks
    int gM  = ((((n + 15) / 16) * 64) + 255) / 256;

    k_zero<<<256, 256>>>(n);
    k_deg<<<gE, 256>>>(col, E);
    k_scan<<<1, 1024>>>(n);
    k_fill<<<gE, 256>>>(row, col, E);
    k_init<<<gNF, 256>>>(x, Wi, We1, n, nobs);

    // edge embedding
    k_gather<<<gHW, 256>>>(hbuf, nagg, n, 1);
    k_gemm<64><<<gG, 256, SMEM64>>>(nagg, nullptr, We2, eemb, n);

    float* cin = curA;
    float* cout = curB;
    for (int l = 0; l < L; l++) {
        k_gather<<<gHW, 256>>>(cin, nagg, n, 0);
        k_gemm<128><<<gG, 256, SMEM128>>>(nagg, eemb, Wmsg + (size_t)l * 8192, msg, n);
        k_gemm<128><<<gG, 256, SMEM128>>>(cin, msg, Wupd + (size_t)l * 8192, cout, n);
        float* tmp = cin; cin = cout; cout = tmp;
    }

    k_means<<<gM, 256>>>(cin, batch, n);
    k_gconst<<<MAXG, 64>>>(Wp, Wr, br);
    k_out<<<gW, 256>>>(cin, batch, Wr, out, n);
}